// round 2
// baseline (speedup 1.0000x reference)
#include <cuda_runtime.h>
#include <cuda_bf16.h>

// SmoothRankAP (1 - mAP with sigmoid rank approximation), B=512, tau=0.01.
//
// Restructure vs reference: sim_pos_rk[b,i] is zero unless target[b,i]==1,
// so sim_all_rk is only needed at positive (b,i) pairs (~B*B/N_CLASSES),
// reducing O(B^3) sigmoids (134M) to O(B * n_pos * B) ~ 4.2M.
// Because label[i]==label[b] for positives, pos_mask[i,j] == target[b,j] (j!=i),
// so each block needs only row b of scores and target.
// Diagonal: sigmoid(0)=0.5 exactly, so summing over ALL j and adding 0.5
// equals (sum_{j!=i} + 1) from the reference.

#define BSZ 512
#define INV_TAU 100.0f
#define NWARP 16
#define NTHREADS 512

__device__ float g_ap[BSZ];

__global__ void __launch_bounds__(NTHREADS)
smoothap_rows_kernel(const float* __restrict__ scores,
                     const float* __restrict__ target) {
    const int b    = blockIdx.x;
    const int tid  = threadIdx.x;
    const int lane = tid & 31;
    const int wid  = tid >> 5;

    __shared__ float s[BSZ];
    __shared__ float t[BSZ];
    __shared__ float warp_ap[NWARP];
    __shared__ float warp_ts[NWARP];

    // Load row b of scores and target (coalesced: one element per thread).
    float tv = target[b * BSZ + tid];
    s[tid] = scores[b * BSZ + tid];
    t[tid] = tv;

    // Warp-reduce target-row sum (n_pos for this b, as float like reference).
    #pragma unroll
    for (int o = 16; o; o >>= 1)
        tv += __shfl_xor_sync(0xffffffffu, tv, o);
    if (lane == 0) warp_ts[wid] = tv;

    __syncthreads();

    // Each warp claims candidate i's in a fixed strided order (deterministic).
    float ap_acc = 0.0f;
    for (int i = wid; i < BSZ; i += NWARP) {
        // Uniform positive test: lane 0 reads t[i], broadcast (1 LDS instead of 32).
        float ti = 0.0f;
        if (lane == 0) ti = t[i];
        ti = __shfl_sync(0xffffffffu, ti, 0);
        if (ti < 0.5f) continue;            // warp-uniform branch

        const float si100 = s[i] * INV_TAU;
        float sa = 0.0f;                    // sum_j sigmoid((s[j]-s[i])/tau)
        float sp = 0.0f;                    // sum_j t[j] * sigmoid(...)
        #pragma unroll
        for (int k = 0; k < BSZ / 32; k++) {
            const int j = lane + k * 32;    // conflict-free: stride-1 in warp
            const float x = fmaf(s[j], INV_TAU, -si100);
            // sigmoid(x) = 1/(1+exp(-x)); saturates correctly:
            //   x >> 0: expf -> 0   -> 1.0
            //   x << 0: expf -> inf -> 1/inf = 0.0
            const float g = __fdividef(1.0f, 1.0f + __expf(-x));
            sa += g;
            sp = fmaf(t[j], g, sp);
        }
        #pragma unroll
        for (int o = 16; o; o >>= 1) {
            sa += __shfl_xor_sync(0xffffffffu, sa, o);
            sp += __shfl_xor_sync(0xffffffffu, sp, o);
        }
        // sim_pos = sp + 0.5 (the +target[b,i]=1 minus the diagonal 0.5*t[i]);
        // sim_all = sa + 0.5 (the +1 minus the diagonal 0.5).
        ap_acc += __fdividef(sp + 0.5f, sa + 0.5f);
    }
    if (lane == 0) warp_ap[wid] = ap_acc;
    __syncthreads();

    if (tid == 0) {
        float total = 0.0f, npos = 0.0f;
        #pragma unroll
        for (int w = 0; w < NWARP; w++) { total += warp_ap[w]; npos += warp_ts[w]; }
        g_ap[b] = total / npos;
    }
}

__global__ void __launch_bounds__(NTHREADS)
smoothap_finalize_kernel(float* __restrict__ out) {
    const int tid  = threadIdx.x;
    const int lane = tid & 31;
    const int wid  = tid >> 5;
    __shared__ float warp_sums[NWARP];

    float v = g_ap[tid];
    #pragma unroll
    for (int o = 16; o; o >>= 1)
        v += __shfl_xor_sync(0xffffffffu, v, o);
    if (lane == 0) warp_sums[wid] = v;
    __syncthreads();

    if (tid == 0) {
        float tot = 0.0f;
        #pragma unroll
        for (int w = 0; w < NWARP; w++) tot += warp_sums[w];
        out[0] = 1.0f - tot * (1.0f / (float)BSZ);
    }
}

extern "C" void kernel_launch(void* const* d_in, const int* in_sizes, int n_in,
                              void* d_out, int out_size) {
    const float* scores = (const float*)d_in[0];
    const float* target = (const float*)d_in[1];
    float* out = (float*)d_out;

    smoothap_rows_kernel<<<BSZ, NTHREADS>>>(scores, target);
    smoothap_finalize_kernel<<<1, NTHREADS>>>(out);
}

// round 3
// speedup vs baseline: 1.3851x; 1.3851x over previous
#include <cuda_runtime.h>
#include <cuda_bf16.h>

// SmoothRankAP (1 - mAP, sigmoid rank approx), B=512, tau=0.01. Fully fused.
//
// Restructure vs reference: sim_pos_rk[b,i]==0 unless target[b,i]==1, so the
// O(B^3) sigmoid tensor collapses to O(B * n_pos * B) ~ 4.2M sigmoids.
// For positives, pos_mask row i == target row b (off-diagonal), so each block
// needs only row b of scores/target. sigmoid(0)=0.5 exactly, so summing over
// ALL j and adding 0.5 reproduces (sum_{j!=i} + 1).
//
// Single kernel: per-block AP + threadfence-reduction final reduce (last
// arriving block reduces g_ap[] in fixed order -> deterministic; resets the
// arrival counter for graph replay).

#define BSZ    512
#define NWARP  16
// (1/tau) * log2(e): sigmoid((sj-si)/tau) = 1/(1 + 2^(si*SCALE - sj*SCALE))
#define SCALE  (100.0f * 1.4426950408889634f)

__device__ float g_ap[BSZ];
__device__ unsigned int g_arrive = 0;

__device__ __forceinline__ float ex2f(float x) {
    float y; asm("ex2.approx.ftz.f32 %0, %1;" : "=f"(y) : "f"(x)); return y;
}
__device__ __forceinline__ float rcpf(float x) {
    float y; asm("rcp.approx.ftz.f32 %0, %1;" : "=f"(y) : "f"(x)); return y;
}

__global__ void __launch_bounds__(BSZ)
smoothap_fused_kernel(const float* __restrict__ scores,
                      const float* __restrict__ target,
                      float* __restrict__ out) {
    const int b    = blockIdx.x;
    const int tid  = threadIdx.x;
    const int lane = tid & 31;
    const int wid  = tid >> 5;

    __shared__ float    s_sc[BSZ];        // scores * SCALE
    __shared__ unsigned t_bits[NWARP];    // target row as bitmask
    __shared__ short    pos_list[BSZ];    // compacted positive indices
    __shared__ int      warp_cnt[NWARP];
    __shared__ float    warp_red[NWARP];
    __shared__ int      s_is_last;

    // Load row b (coalesced), pre-scale scores, ballot target bits.
    const float tv = target[b * BSZ + tid];
    s_sc[tid] = scores[b * BSZ + tid] * SCALE;
    const unsigned m = __ballot_sync(0xffffffffu, tv > 0.5f);
    if (lane == 0) { t_bits[wid] = m; warp_cnt[wid] = __popc(m); }
    __syncthreads();

    // Deterministic compaction of positive indices.
    int base = 0, npos = 0;
    #pragma unroll
    for (int w = 0; w < NWARP; w++) {
        const int c = warp_cnt[w];
        if (w < wid) base += c;
        npos += c;
    }
    if (tv > 0.5f) {
        const int rank = __popc(m & ((1u << lane) - 1u));
        pos_list[base + rank] = (short)tid;
    }
    __syncthreads();

    // Each warp handles positives p = wid, wid+16, ... (fixed order).
    float ap_acc = 0.0f;
    for (int p = wid; p < npos; p += NWARP) {
        const int   i  = pos_list[p];
        const float si = s_sc[i];                 // LDS broadcast
        float sa = 0.0f, sp = 0.0f;
        #pragma unroll
        for (int k = 0; k < BSZ / 32; k++) {
            const int j = k * 32 + lane;          // conflict-free
            // sigmoid((sj-si)/tau) = 1/(1+2^(si-sj))  (in scaled units)
            const float g = rcpf(1.0f + ex2f(si - s_sc[j]));
            sa += g;
            if ((t_bits[k] >> lane) & 1u) sp += g;
        }
        #pragma unroll
        for (int o = 16; o; o >>= 1) {
            sa += __shfl_xor_sync(0xffffffffu, sa, o);
            sp += __shfl_xor_sync(0xffffffffu, sp, o);
        }
        // +0.5 = (+1 from reference) - (diagonal sigmoid(0)=0.5 counted above)
        ap_acc += __fdividef(sp + 0.5f, sa + 0.5f);
    }
    if (lane == 0) warp_red[wid] = ap_acc;
    __syncthreads();

    if (tid == 0) {
        float total = 0.0f;
        #pragma unroll
        for (int w = 0; w < NWARP; w++) total += warp_red[w];
        g_ap[b] = total / (float)npos;
        __threadfence();                           // release g_ap[b]
        const unsigned old = atomicAdd(&g_arrive, 1u);
        s_is_last = (old == (unsigned)(gridDim.x - 1));
        if (s_is_last) __threadfence();            // acquire others' g_ap
    }
    __syncthreads();

    // Last-arriving block does the final reduction (fixed order, deterministic).
    if (s_is_last) {
        float v = g_ap[tid];
        #pragma unroll
        for (int o = 16; o; o >>= 1)
            v += __shfl_xor_sync(0xffffffffu, v, o);
        __syncthreads();                           // warp_red reuse
        if (lane == 0) warp_red[wid] = v;
        __syncthreads();
        if (tid == 0) {
            float tot = 0.0f;
            #pragma unroll
            for (int w = 0; w < NWARP; w++) tot += warp_red[w];
            out[0] = 1.0f - tot * (1.0f / (float)BSZ);
            g_arrive = 0;                          // reset for next graph replay
        }
    }
}

extern "C" void kernel_launch(void* const* d_in, const int* in_sizes, int n_in,
                              void* d_out, int out_size) {
    const float* scores = (const float*)d_in[0];
    const float* target = (const float*)d_in[1];
    float* out = (float*)d_out;
    smoothap_fused_kernel<<<BSZ, BSZ>>>(scores, target, out);
}